// round 3
// baseline (speedup 1.0000x reference)
#include <cuda_runtime.h>
#include <cstdint>

#define B_   64
#define T_   4096
#define NIN  64
#define U_   128
#define NOUT 64
#define CCH  64     // chunks
#define LCH  64     // chunk length (timesteps)
#define HT   2048   // T_/2  (odd-state count per batch)
#define HCH  32     // odd states per chunk

// ---------------------------------------------------------------------------
// Static device scratch
// ---------------------------------------------------------------------------
__device__ float g_Ky[B_ * T_ * U_];    // 128 MB
__device__ float g_Z[B_ * HT * U_];     // 64 MB  Z_i = ky[2i+1] + ky[2i]@A
__device__ float g_S[B_ * HT * U_];     // 64 MB  odd states e_i (chunk-local)
__device__ float g_carry[B_ * CCH * U_];
__device__ float g_A2[U_ * U_], g_A4[U_ * U_], g_A8[U_ * U_];
__device__ float g_A16[U_ * U_], g_A32[U_ * U_], g_A64[U_ * U_];
__device__ float g_Wt[U_ * LCH * NOUT]; // [k][step][o]; W[s] = A^(s+1) @ CyT

// ---------------------------------------------------------------------------
// Packed f32x2 helpers
// ---------------------------------------------------------------------------
__device__ __forceinline__ unsigned long long ffma2(unsigned long long a,
                                                    unsigned long long b,
                                                    unsigned long long c) {
    unsigned long long d;
    asm("fma.rn.f32x2 %0, %1, %2, %3;" : "=l"(d) : "l"(a), "l"(b), "l"(c));
    return d;
}
__device__ __forceinline__ unsigned long long dup2(float v) {
    unsigned long long r;
    asm("mov.b64 %0, {%1, %1};" : "=l"(r) : "f"(v));
    return r;
}
__device__ __forceinline__ unsigned long long pack2(float x, float y) {
    unsigned long long r;
    asm("mov.b64 %0, {%1, %2};" : "=l"(r) : "f"(x), "f"(y));
    return r;
}
__device__ __forceinline__ float2 unpack2(unsigned long long v) {
    float2 f;
    asm("mov.b64 {%0, %1}, %2;" : "=f"(f.x), "=f"(f.y) : "l"(v));
    return f;
}

// 8m x 4n register-tile MAC step: a-pairs packed, b duplicated.
template <int BSTRIDE>
__device__ __forceinline__ void mma8x4(unsigned long long acc[4][4],
                                       const float* __restrict__ As,
                                       const float* __restrict__ Bs,
                                       int k, int m0, int n4) {
    const ulonglong2 a01 = *(const ulonglong2*)&As[k * 64 + m0];
    const ulonglong2 a23 = *(const ulonglong2*)&As[k * 64 + m0 + 4];
    const float4 bv = *(const float4*)&Bs[k * BSTRIDE + n4];
    const unsigned long long b0 = dup2(bv.x), b1 = dup2(bv.y);
    const unsigned long long b2 = dup2(bv.z), b3 = dup2(bv.w);
    acc[0][0] = ffma2(a01.x, b0, acc[0][0]);
    acc[0][1] = ffma2(a01.x, b1, acc[0][1]);
    acc[0][2] = ffma2(a01.x, b2, acc[0][2]);
    acc[0][3] = ffma2(a01.x, b3, acc[0][3]);
    acc[1][0] = ffma2(a01.y, b0, acc[1][0]);
    acc[1][1] = ffma2(a01.y, b1, acc[1][1]);
    acc[1][2] = ffma2(a01.y, b2, acc[1][2]);
    acc[1][3] = ffma2(a01.y, b3, acc[1][3]);
    acc[2][0] = ffma2(a23.x, b0, acc[2][0]);
    acc[2][1] = ffma2(a23.x, b1, acc[2][1]);
    acc[2][2] = ffma2(a23.x, b2, acc[2][2]);
    acc[2][3] = ffma2(a23.x, b3, acc[2][3]);
    acc[3][0] = ffma2(a23.y, b0, acc[3][0]);
    acc[3][1] = ffma2(a23.y, b1, acc[3][1]);
    acc[3][2] = ffma2(a23.y, b2, acc[3][2]);
    acc[3][3] = ffma2(a23.y, b3, acc[3][3]);
}

// ---------------------------------------------------------------------------
// K1: Ky = x @ KT
// ---------------------------------------------------------------------------
__global__ __launch_bounds__(128) void ky_kernel(const float* __restrict__ x,
                                                 const float* __restrict__ KT) {
    const int u = threadIdx.x;
    float kt[NIN];
#pragma unroll
    for (int n = 0; n < NIN; n++) kt[n] = KT[n * U_ + u];

    __shared__ __align__(16) float xs[NIN * 8];
    const int row0 = blockIdx.x * 256;

#pragma unroll 1
    for (int tile = 0; tile < 32; tile++) {
        const int r0 = row0 + tile * 8;
        float4 xv = reinterpret_cast<const float4*>(x + (size_t)r0 * NIN)[u];
        __syncthreads();
        {
            const int rr = u >> 4;
            const int n0 = (u & 15) * 4;
            xs[(n0 + 0) * 8 + rr] = xv.x;
            xs[(n0 + 1) * 8 + rr] = xv.y;
            xs[(n0 + 2) * 8 + rr] = xv.z;
            xs[(n0 + 3) * 8 + rr] = xv.w;
        }
        __syncthreads();

        unsigned long long acc[4] = {0ull, 0ull, 0ull, 0ull};
#pragma unroll
        for (int n = 0; n < NIN; n++) {
            unsigned long long kv = dup2(kt[n]);
            ulonglong2 a = *reinterpret_cast<const ulonglong2*>(&xs[n * 8]);
            ulonglong2 b = *reinterpret_cast<const ulonglong2*>(&xs[n * 8 + 4]);
            acc[0] = ffma2(a.x, kv, acc[0]);
            acc[1] = ffma2(a.y, kv, acc[1]);
            acc[2] = ffma2(b.x, kv, acc[2]);
            acc[3] = ffma2(b.y, kv, acc[3]);
        }
#pragma unroll
        for (int i = 0; i < 4; i++) {
            float2 f = unpack2(acc[i]);
            g_Ky[(size_t)(r0 + 2 * i)     * U_ + u] = f.x;
            g_Ky[(size_t)(r0 + 2 * i + 1) * U_ + u] = f.y;
        }
    }
}

// ---------------------------------------------------------------------------
// K2: Z[b,i] = ky[2i+1] + ky[2i]@A.  GEMM M=131072, N=128, K=128.
// CTA: 64 rows x 128 cols, 256 threads, dynamic smem 96KB.
// ---------------------------------------------------------------------------
__global__ __launch_bounds__(256) void zbuild(const float* __restrict__ A) {
    extern __shared__ float sm[];
    float* As = sm;           // [128][64]  transposed even-ky rows
    float* Bs = sm + 8192;    // [128][128] A
    const int tid = threadIdx.x;
    const int row0 = blockIdx.x * 64;

    {   // As
        const int mi = tid >> 2, kq = (tid & 3) * 32;
        const int r = row0 + mi;
        const int b = r >> 11, i = r & (HT - 1);
        const float* src = g_Ky + ((size_t)b * T_ + 2 * i) * U_ + kq;
#pragma unroll
        for (int j = 0; j < 32; j += 4) {
            float4 v = *(const float4*)(src + j);
            As[(kq + j + 0) * 64 + mi] = v.x;
            As[(kq + j + 1) * 64 + mi] = v.y;
            As[(kq + j + 2) * 64 + mi] = v.z;
            As[(kq + j + 3) * 64 + mi] = v.w;
        }
    }
    {   // Bs = A
        const int k = tid >> 1, h = (tid & 1) * 64;
        const float4* src = (const float4*)(A + k * U_ + h);
        float4* dst = (float4*)(Bs + k * U_ + h);
#pragma unroll
        for (int j = 0; j < 16; j++) dst[j] = src[j];
    }
    __syncthreads();

    const int ni = tid & 31, mg = tid >> 5;
    const int n4 = ni * 4, m0 = mg * 8;
    unsigned long long acc[4][4] = {};
#pragma unroll 16
    for (int k = 0; k < U_; k++) mma8x4<128>(acc, As, Bs, k, m0, n4);

#pragma unroll
    for (int p = 0; p < 4; p++) {
        float2 q0 = unpack2(acc[p][0]), q1 = unpack2(acc[p][1]);
        float2 q2 = unpack2(acc[p][2]), q3 = unpack2(acc[p][3]);
        const int r = row0 + m0 + 2 * p;
        const int b = r >> 11, i = r & (HT - 1);
        float4 kv0 = *(const float4*)(g_Ky + ((size_t)b * T_ + 2 * i + 1) * U_ + n4);
        *(float4*)(g_Z + (size_t)r * U_ + n4) =
            make_float4(q0.x + kv0.x, q1.x + kv0.y, q2.x + kv0.z, q3.x + kv0.w);
        float4 kv1 = *(const float4*)(g_Ky + ((size_t)b * T_ + 2 * i + 3) * U_ + n4);
        *(float4*)(g_Z + (size_t)(r + 1) * U_ + n4) =
            make_float4(q0.y + kv1.x, q1.y + kv1.y, q2.y + kv1.z, q3.y + kv1.w);
    }
}

// ---------------------------------------------------------------------------
// K3: matsq  O = A @ A
// ---------------------------------------------------------------------------
__global__ __launch_bounds__(128) void matsq(const float* __restrict__ A,
                                             float* __restrict__ O) {
    const int r = blockIdx.x, u = threadIdx.x;
    __shared__ float row[U_];
    row[u] = A[r * U_ + u];
    __syncthreads();
    float a0 = 0.f, a1 = 0.f, a2 = 0.f, a3 = 0.f;
#pragma unroll
    for (int k = 0; k < U_; k += 4) {
        a0 = fmaf(row[k + 0], A[(k + 0) * U_ + u], a0);
        a1 = fmaf(row[k + 1], A[(k + 1) * U_ + u], a1);
        a2 = fmaf(row[k + 2], A[(k + 2) * U_ + u], a2);
        a3 = fmaf(row[k + 3], A[(k + 3) * U_ + u], a3);
    }
    O[r * U_ + u] = (a0 + a1) + (a2 + a3);
}

// ---------------------------------------------------------------------------
// K4: radix-2 scan.  e_i = Z_i + e_{i-1} @ A2, 32 steps per chunk.
// 16 batches/CTA; grid (64 chunks, 2 batch-groups) per launch (split in two).
// ---------------------------------------------------------------------------
__global__ __launch_bounds__(128, 2) void scan_kernel(int bgbase) {
    const int c = blockIdx.x, bg = blockIdx.y + bgbase, u = threadIdx.x;
    const int b0 = bg * 16;

    __shared__ __align__(16) float s_sh[2][U_ * 16];

    float at2[U_];
#pragma unroll
    for (int k = 0; k < U_; k++) at2[k] = g_A2[k * U_ + u];

#pragma unroll
    for (int j = 0; j < 16; j++) s_sh[0][u * 16 + j] = 0.f;
    __syncthreads();

    const int i0 = c * HCH;
    float zc[16];
#pragma unroll
    for (int j = 0; j < 16; j++)
        zc[j] = g_Z[((size_t)(b0 + j) * HT + i0) * U_ + u];

    int p = 0;
#pragma unroll 1
    for (int it = 0; it < HCH; it++) {
        const int i = i0 + it;

        float zn[16];
        if (it < HCH - 1) {
#pragma unroll
            for (int j = 0; j < 16; j++)
                zn[j] = g_Z[((size_t)(b0 + j) * HT + i + 1) * U_ + u];
        } else {
#pragma unroll
            for (int j = 0; j < 16; j++) zn[j] = 0.f;
        }

        unsigned long long acc[8];
#pragma unroll
        for (int q = 0; q < 8; q++) acc[q] = pack2(zc[2 * q], zc[2 * q + 1]);

#pragma unroll
        for (int k = 0; k < U_; k++) {
            const unsigned long long av = dup2(at2[k]);
            const ulonglong2 s0 = *(const ulonglong2*)&s_sh[p][k * 16 + 0];
            const ulonglong2 s1 = *(const ulonglong2*)&s_sh[p][k * 16 + 4];
            const ulonglong2 s2 = *(const ulonglong2*)&s_sh[p][k * 16 + 8];
            const ulonglong2 s3 = *(const ulonglong2*)&s_sh[p][k * 16 + 12];
            acc[0] = ffma2(s0.x, av, acc[0]);
            acc[1] = ffma2(s0.y, av, acc[1]);
            acc[2] = ffma2(s1.x, av, acc[2]);
            acc[3] = ffma2(s1.y, av, acc[3]);
            acc[4] = ffma2(s2.x, av, acc[4]);
            acc[5] = ffma2(s2.y, av, acc[5]);
            acc[6] = ffma2(s3.x, av, acc[6]);
            acc[7] = ffma2(s3.y, av, acc[7]);
        }

        const int q = p ^ 1;
        {
            float2 f0 = unpack2(acc[0]), f1 = unpack2(acc[1]);
            float2 f2 = unpack2(acc[2]), f3 = unpack2(acc[3]);
            float2 f4 = unpack2(acc[4]), f5 = unpack2(acc[5]);
            float2 f6 = unpack2(acc[6]), f7 = unpack2(acc[7]);
            float4* dst = (float4*)&s_sh[q][u * 16];
            dst[0] = make_float4(f0.x, f0.y, f1.x, f1.y);
            dst[1] = make_float4(f2.x, f2.y, f3.x, f3.y);
            dst[2] = make_float4(f4.x, f4.y, f5.x, f5.y);
            dst[3] = make_float4(f6.x, f6.y, f7.x, f7.y);
            // write states to global (coalesced across u)
            g_S[((size_t)(b0 + 0)  * HT + i) * U_ + u] = f0.x;
            g_S[((size_t)(b0 + 1)  * HT + i) * U_ + u] = f0.y;
            g_S[((size_t)(b0 + 2)  * HT + i) * U_ + u] = f1.x;
            g_S[((size_t)(b0 + 3)  * HT + i) * U_ + u] = f1.y;
            g_S[((size_t)(b0 + 4)  * HT + i) * U_ + u] = f2.x;
            g_S[((size_t)(b0 + 5)  * HT + i) * U_ + u] = f2.y;
            g_S[((size_t)(b0 + 6)  * HT + i) * U_ + u] = f3.x;
            g_S[((size_t)(b0 + 7)  * HT + i) * U_ + u] = f3.y;
            g_S[((size_t)(b0 + 8)  * HT + i) * U_ + u] = f4.x;
            g_S[((size_t)(b0 + 9)  * HT + i) * U_ + u] = f4.y;
            g_S[((size_t)(b0 + 10) * HT + i) * U_ + u] = f5.x;
            g_S[((size_t)(b0 + 11) * HT + i) * U_ + u] = f5.y;
            g_S[((size_t)(b0 + 12) * HT + i) * U_ + u] = f6.x;
            g_S[((size_t)(b0 + 13) * HT + i) * U_ + u] = f6.y;
            g_S[((size_t)(b0 + 14) * HT + i) * U_ + u] = f7.x;
            g_S[((size_t)(b0 + 15) * HT + i) * U_ + u] = f7.y;
        }
        __syncthreads();

        p = q;
#pragma unroll
        for (int j = 0; j < 16; j++) zc[j] = zn[j];
    }
}

// ---------------------------------------------------------------------------
// K5: carry scan. carry[b,0]=0; carry[b,c] = E[b,c-1] + carry[b,c-1]@A64
// E[b,c] = g_S[b][c*32+31] (chunk-end local state)
// ---------------------------------------------------------------------------
__global__ __launch_bounds__(128) void pass2_kernel() {
    const int b = blockIdx.x, u = threadIdx.x;
    __shared__ float ss[2][U_];
    float m[U_];
#pragma unroll
    for (int k = 0; k < U_; k++) m[k] = g_A64[k * U_ + u];

    float su = 0.f;
    float e = g_S[((size_t)b * HT + (HCH - 1)) * U_ + u];
    ss[0][u] = 0.f;
    __syncthreads();

    int p = 0;
#pragma unroll 1
    for (int c = 0; c < CCH; c++) {
        g_carry[((size_t)b * CCH + c) * U_ + u] = su;
        float a0 = e, a1 = 0.f, a2 = 0.f, a3 = 0.f;
        if (c < CCH - 1)
            e = g_S[((size_t)b * HT + (c + 1) * HCH + (HCH - 1)) * U_ + u];
#pragma unroll
        for (int k = 0; k < U_; k += 4) {
            a0 = fmaf(ss[p][k + 0], m[k + 0], a0);
            a1 = fmaf(ss[p][k + 1], m[k + 1], a1);
            a2 = fmaf(ss[p][k + 2], m[k + 2], a2);
            a3 = fmaf(ss[p][k + 3], m[k + 3], a3);
        }
        su = (a0 + a1) + (a2 + a3);
        ss[p ^ 1][u] = su;
        __syncthreads();
        p ^= 1;
    }
}

// ---------------------------------------------------------------------------
// K6: W build (verified in R2). Block j: Wt[:, sout+j, :] = P_j @ Win[j]
// ---------------------------------------------------------------------------
__global__ __launch_bounds__(512) void wdouble(const float* __restrict__ Pa,
                                               const float* __restrict__ Pb,
                                               const float* __restrict__ Win,
                                               int win_rs, int jstride, int sout) {
    const int j = blockIdx.x;
    const float* P = (j & 1) ? Pb : Pa;
    __shared__ float win_sh[U_ * NOUT];
    const int tid = threadIdx.x;
    for (int idx = tid; idx < U_ * NOUT; idx += 512) {
        int m = idx >> 6, o = idx & 63;
        win_sh[idx] = Win[m * win_rs + j * jstride + o];
    }
    __syncthreads();
    const int o = tid & 63, kg = tid >> 6;
#pragma unroll 1
    for (int ki = 0; ki < 16; ki++) {
        const int k = kg * 16 + ki;
        float a0 = 0.f, a1 = 0.f, a2 = 0.f, a3 = 0.f;
#pragma unroll
        for (int m = 0; m < U_; m += 4) {
            a0 = fmaf(P[k * U_ + m + 0], win_sh[(m + 0) * 64 + o], a0);
            a1 = fmaf(P[k * U_ + m + 1], win_sh[(m + 1) * 64 + o], a1);
            a2 = fmaf(P[k * U_ + m + 2], win_sh[(m + 2) * 64 + o], a2);
            a3 = fmaf(P[k * U_ + m + 3], win_sh[(m + 3) * 64 + o], a3);
        }
        g_Wt[(size_t)k * (LCH * NOUT) + (sout + j) * 64 + o] = (a0 + a1) + (a2 + a3);
    }
}

// ---------------------------------------------------------------------------
// K7: y = carry @ Wt  (WRITES y).  M=4096 (b,c), N=4096 (step,o), K=128.
// ---------------------------------------------------------------------------
__global__ __launch_bounds__(128, 2) void fixup(float* __restrict__ y) {
    const int nt = blockIdx.x, mt = blockIdx.y;
    const int tid = threadIdx.x;
    __shared__ __align__(16) float As[U_ * 64];
    __shared__ __align__(16) float Bs[U_ * 32];

    {
        const int mi = tid >> 1, kh = (tid & 1) * 64;
        const float* src = &g_carry[((size_t)(mt * 64 + mi)) * U_ + kh];
#pragma unroll
        for (int i = 0; i < 64; i += 4) {
            float4 v = *(const float4*)(src + i);
            As[(kh + i + 0) * 64 + mi] = v.x;
            As[(kh + i + 1) * 64 + mi] = v.y;
            As[(kh + i + 2) * 64 + mi] = v.z;
            As[(kh + i + 3) * 64 + mi] = v.w;
        }
    }
    {
        const float4* src = (const float4*)&g_Wt[(size_t)tid * (LCH * NOUT) + nt * 32];
        float4* dst = (float4*)&Bs[tid * 32];
#pragma unroll
        for (int i = 0; i < 8; i++) dst[i] = src[i];
    }
    __syncthreads();

    const int ni = tid & 7, mi = tid >> 3;
    const int n4 = ni * 4, m4 = mi * 4;

    unsigned long long acc[4][2];
#pragma unroll
    for (int i = 0; i < 4; i++) { acc[i][0] = 0ull; acc[i][1] = 0ull; }

#pragma unroll 8
    for (int k = 0; k < U_; k++) {
        const float4 a = *(const float4*)&As[k * 64 + m4];
        const ulonglong2 b = *(const ulonglong2*)&Bs[k * 32 + n4];
        const unsigned long long a0 = dup2(a.x), a1 = dup2(a.y);
        const unsigned long long a2 = dup2(a.z), a3 = dup2(a.w);
        acc[0][0] = ffma2(b.x, a0, acc[0][0]);
        acc[0][1] = ffma2(b.y, a0, acc[0][1]);
        acc[1][0] = ffma2(b.x, a1, acc[1][0]);
        acc[1][1] = ffma2(b.y, a1, acc[1][1]);
        acc[2][0] = ffma2(b.x, a2, acc[2][0]);
        acc[2][1] = ffma2(b.y, a2, acc[2][1]);
        acc[3][0] = ffma2(b.x, a3, acc[3][0]);
        acc[3][1] = ffma2(b.y, a3, acc[3][1]);
    }

#pragma unroll
    for (int i = 0; i < 4; i++) {
        const int r = mt * 64 + m4 + i;
        float* yp = y + (size_t)r * 4096 + nt * 32 + n4;
        float2 f0 = unpack2(acc[i][0]), f1 = unpack2(acc[i][1]);
        *(float4*)yp = make_float4(f0.x, f0.y, f1.x, f1.y);
    }
}

// ---------------------------------------------------------------------------
// K8a: y[b,2i+1,:] += e_i @ CyT.  M=131072, N=64, K=128. 64KB dyn smem.
// ---------------------------------------------------------------------------
__global__ __launch_bounds__(128) void k8a(const float* __restrict__ CyT,
                                           float* __restrict__ y) {
    extern __shared__ float sm[];
    float* As = sm;          // [128][64]
    float* Bs = sm + 8192;   // [128][64]
    const int tid = threadIdx.x;
    const int row0 = blockIdx.x * 64;

    {
        const int mi = tid >> 1, kh = (tid & 1) * 64;
        const int r = row0 + mi;
        const int b = r >> 11, i = r & (HT - 1);
        const float* src = g_S + ((size_t)b * HT + i) * U_ + kh;
#pragma unroll
        for (int j = 0; j < 64; j += 4) {
            float4 v = *(const float4*)(src + j);
            As[(kh + j + 0) * 64 + mi] = v.x;
            As[(kh + j + 1) * 64 + mi] = v.y;
            As[(kh + j + 2) * 64 + mi] = v.z;
            As[(kh + j + 3) * 64 + mi] = v.w;
        }
    }
    {
        const float4* src = (const float4*)(CyT + tid * 64);
        float4* dst = (float4*)(Bs + tid * 64);
#pragma unroll
        for (int j = 0; j < 16; j++) dst[j] = src[j];
    }
    __syncthreads();

    const int ni = tid & 15, mg = tid >> 4;
    const int n4 = ni * 4, m0 = mg * 8;
    unsigned long long acc[4][4] = {};
#pragma unroll 16
    for (int k = 0; k < U_; k++) mma8x4<64>(acc, As, Bs, k, m0, n4);

#pragma unroll
    for (int p = 0; p < 4; p++) {
        float2 q0 = unpack2(acc[p][0]), q1 = unpack2(acc[p][1]);
        float2 q2 = unpack2(acc[p][2]), q3 = unpack2(acc[p][3]);
        const int r = row0 + m0 + 2 * p;
        const int b = r >> 11, i = r & (HT - 1);
        float* y0 = y + ((size_t)b * T_ + 2 * i + 1) * NOUT + n4;
        float4 e0 = *(float4*)y0;
        *(float4*)y0 = make_float4(e0.x + q0.x, e0.y + q1.x, e0.z + q2.x, e0.w + q3.x);
        float* y1 = y + ((size_t)b * T_ + 2 * (i + 1) + 1) * NOUT + n4;
        float4 e1 = *(float4*)y1;
        *(float4*)y1 = make_float4(e1.x + q0.y, e1.y + q1.y, e1.z + q2.y, e1.w + q3.y);
    }
}

// ---------------------------------------------------------------------------
// K8b: y[b,2i,:] += ky[2i]@CyT + eprev_i@ACyT.  Two-phase, 64KB dyn smem.
// ACyT = Wt[:,0,:].
// ---------------------------------------------------------------------------
__global__ __launch_bounds__(128) void k8b(const float* __restrict__ CyT,
                                           float* __restrict__ y) {
    extern __shared__ float sm[];
    float* As = sm;
    float* Bs = sm + 8192;
    const int tid = threadIdx.x;
    const int row0 = blockIdx.x * 64;
    const int ni = tid & 15, mg = tid >> 4;
    const int n4 = ni * 4, m0 = mg * 8;

    unsigned long long acc[4][4] = {};

    // ---- phase 1: ky_even @ CyT ----
    {
        const int mi = tid >> 1, kh = (tid & 1) * 64;
        const int r = row0 + mi;
        const int b = r >> 11, i = r & (HT - 1);
        const float* src = g_Ky + ((size_t)b * T_ + 2 * i) * U_ + kh;
#pragma unroll
        for (int j = 0; j < 64; j += 4) {
            float4 v = *(const float4*)(src + j);
            As[(kh + j + 0) * 64 + mi] = v.x;
            As[(kh + j + 1) * 64 + mi] = v.y;
            As[(kh + j + 2) * 64 + mi] = v.z;
            As[(kh + j + 3) * 64 + mi] = v.w;
        }
        const float4* csrc = (const float4*)(CyT + tid * 64);
        float4* cdst = (float4*)(Bs + tid * 64);
#pragma unroll
        for (int j = 0; j < 16; j++) cdst[j] = csrc[j];
    }
    __syncthreads();
#pragma unroll 16
    for (int k = 0; k < U_; k++) mma8x4<64>(acc, As, Bs, k, m0, n4);
    __syncthreads();

    // ---- phase 2: eprev @ ACyT ----
    {
        const int mi = tid >> 1, kh = (tid & 1) * 64;
        const int r = row0 + mi;
        const int b = r >> 11, i = r & (HT - 1);
        if ((i & (HCH - 1)) == 0) {
#pragma unroll
            for (int j = 0; j < 64; j++) As[(kh + j) * 64 + mi] = 0.f;
        } else {
            const float* src = g_S + ((size_t)b * HT + i - 1) * U_ + kh;
#pragma unroll
            for (int j = 0; j < 64; j += 4) {
                float4 v = *(const float4*)(src + j);
                As[(kh + j + 0) * 64 + mi] = v.x;
                As[(kh + j + 1) * 64 + mi] = v.y;
                As[(kh + j + 2) * 64 + mi] = v.z;
                As[(kh + j + 3) * 64 + mi] = v.w;
            }
        }
        // Bs = ACyT = Wt[k][0][o]
        const float4* wsrc = (const float4*)(g_Wt + (size_t)tid * (LCH * NOUT));
        float4* wdst = (float4*)(Bs + tid * 64);
#pragma unroll
        for (int j = 0; j < 16; j++) wdst[j] = wsrc[j];
    }
    __syncthreads();
#pragma unroll 16
    for (int k = 0; k < U_; k++) mma8x4<64>(acc, As, Bs, k, m0, n4);

#pragma unroll
    for (int p = 0; p < 4; p++) {
        float2 q0 = unpack2(acc[p][0]), q1 = unpack2(acc[p][1]);
        float2 q2 = unpack2(acc[p][2]), q3 = unpack2(acc[p][3]);
        const int r = row0 + m0 + 2 * p;
        const int b = r >> 11, i = r & (HT - 1);
        float* y0 = y + ((size_t)b * T_ + 2 * i) * NOUT + n4;
        float4 e0 = *(float4*)y0;
        *(float4*)y0 = make_float4(e0.x + q0.x, e0.y + q1.x, e0.z + q2.x, e0.w + q3.x);
        float* y1 = y + ((size_t)b * T_ + 2 * (i + 1)) * NOUT + n4;
        float4 e1 = *(float4*)y1;
        *(float4*)y1 = make_float4(e1.x + q0.y, e1.y + q1.y, e1.z + q2.y, e1.w + q3.y);
    }
}

// ---------------------------------------------------------------------------
// Launch
// ---------------------------------------------------------------------------
extern "C" void kernel_launch(void* const* d_in, const int* in_sizes, int n_in,
                              void* d_out, int out_size) {
    const float* x   = (const float*)d_in[0];
    const float* AT  = (const float*)d_in[1];
    const float* KT  = (const float*)d_in[2];
    const float* CyT = (const float*)d_in[3];
    float* y = (float*)d_out;

    float *A2, *A4, *A8, *A16, *A32, *A64, *Wt;
    cudaGetSymbolAddress((void**)&A2,  g_A2);
    cudaGetSymbolAddress((void**)&A4,  g_A4);
    cudaGetSymbolAddress((void**)&A8,  g_A8);
    cudaGetSymbolAddress((void**)&A16, g_A16);
    cudaGetSymbolAddress((void**)&A32, g_A32);
    cudaGetSymbolAddress((void**)&A64, g_A64);
    cudaGetSymbolAddress((void**)&Wt,  g_Wt);

    static bool attr_done = false;
    if (!attr_done) {
        cudaFuncSetAttribute(zbuild, cudaFuncAttributeMaxDynamicSharedMemorySize, 98304);
        cudaFuncSetAttribute(k8a, cudaFuncAttributeMaxDynamicSharedMemorySize, 65536);
        cudaFuncSetAttribute(k8b, cudaFuncAttributeMaxDynamicSharedMemorySize, 65536);
        attr_done = true;
    }

    ky_kernel<<<(B_ * T_) / 256, 128>>>(x, KT);                 // 1
    zbuild<<<(B_ * HT) / 64, 256, 98304>>>(AT);                 // 2
    matsq<<<128, 128>>>(AT,  A2);                               // 3
    matsq<<<128, 128>>>(A2,  A4);                               // 4
    scan_kernel<<<dim3(CCH, 2), 128>>>(0);                      // 5  <- ncu
    scan_kernel<<<dim3(CCH, 2), 128>>>(2);                      // 6  <- ncu
    matsq<<<128, 128>>>(A4,  A8);                               // 7
    matsq<<<128, 128>>>(A8,  A16);                              // 8
    matsq<<<128, 128>>>(A16, A32);                              // 9
    matsq<<<128, 128>>>(A32, A64);                              // 10
    pass2_kernel<<<B_, 128>>>();                                // 11

    wdouble<<<2, 512>>>(AT,  A2,  CyT, 64,   0,  0);            // 12
    wdouble<<<2, 512>>>(A2,  A2,  Wt,  4096, 64, 2);            // 13
    wdouble<<<4, 512>>>(A4,  A4,  Wt,  4096, 64, 4);            // 14
    wdouble<<<8, 512>>>(A8,  A8,  Wt,  4096, 64, 8);            // 15
    wdouble<<<16, 512>>>(A16, A16, Wt, 4096, 64, 16);           // 16
    wdouble<<<32, 512>>>(A32, A32, Wt, 4096, 64, 32);           // 17

    fixup<<<dim3(128, 64), 128>>>(y);                           // 18 (writes y)
    k8a<<<(B_ * HT) / 64, 128, 65536>>>(CyT, y);                // 19 (+=)
    k8b<<<(B_ * HT) / 64, 128, 65536>>>(CyT, y);                // 20 (+=)
}